// round 8
// baseline (speedup 1.0000x reference)
#include <cuda_runtime.h>
#include <cuda_fp16.h>
#include <cstdint>
#include <math.h>

// ---------------- problem constants ----------------
#define B_    128
#define T_    512
#define PT_   16
#define SKIP_ 32
#define NSEQ  4096

// ---------------- device-global scratch ----------------
__device__ __half g_xp16[16u * 4096u * 512u];    // x packed fp16 (hi only)
__device__ __half g_wp16[1536u * 1024u];         // W packed hi|lo (gate-interleaved cols)
__device__ __half g_up16[1536u * 1024u];         // U packed hi|lo
__device__ float  g_xpf[65536u * 1536u];         // XP = x@W, packed col layout
__device__ float  g_hf[2][NSEQ * 512u];          // hidden fp32 ping-pong
__device__ __half g_hp16[2][NSEQ * 512u];        // hidden fp16 ping-pong

// ---------------- smem layout (per stage, KC=32, rows padded 64B->80B) ----------------
// A: 128 rows * 80 = 10240 ; B: 192 rows (96 hi + 96 lo) * 80 = 15360
#define ROWB        80
#define OFF_B       10240
#define STAGE_BYTES 25600
#define NBUF        3
#define SMEM_BYTES  (NBUF * STAGE_BYTES)   // 76800

// ---------------- helpers ----------------
__device__ __forceinline__ uint32_t smem_u32(const void* p) {
    uint32_t a;
    asm("{ .reg .u64 t; cvta.to.shared.u64 t, %1; cvt.u32.u64 %0, t; }" : "=r"(a) : "l"(p));
    return a;
}
__device__ __forceinline__ void cp_async16(uint32_t s, const void* g) {
    asm volatile("cp.async.cg.shared.global [%0], [%1], 16;" :: "r"(s), "l"(g) : "memory");
}
__device__ __forceinline__ void cp_commit() { asm volatile("cp.async.commit_group;" ::: "memory"); }
template <int N> __device__ __forceinline__ void cp_wait() { asm volatile("cp.async.wait_group %0;" :: "n"(N) : "memory"); }

__device__ __forceinline__ void ldm4(uint32_t addr, uint32_t* r) {
    asm volatile("ldmatrix.sync.aligned.m8n8.x4.shared.b16 {%0,%1,%2,%3}, [%4];"
                 : "=r"(r[0]), "=r"(r[1]), "=r"(r[2]), "=r"(r[3]) : "r"(addr));
}
__device__ __forceinline__ void mma16816(float* d, const uint32_t* a, const uint32_t* b) {
    asm volatile("mma.sync.aligned.m16n8k16.row.col.f32.f16.f16.f32 "
                 "{%0,%1,%2,%3},{%4,%5,%6,%7},{%8,%9},{%0,%1,%2,%3};"
                 : "+f"(d[0]), "+f"(d[1]), "+f"(d[2]), "+f"(d[3])
                 : "r"(a[0]), "r"(a[1]), "r"(a[2]), "r"(a[3]), "r"(b[0]), "r"(b[1]));
}
__device__ __forceinline__ float sigmoidf_(float x) { return 1.f / (1.f + __expf(-x)); }

// ---------------- pack kernels ----------------
__global__ __launch_bounds__(256) void pack_wu16(const float* __restrict__ W, const float* __restrict__ U,
                                                 __half* __restrict__ Wp, __half* __restrict__ Up) {
    int idx = blockIdx.x * 256 + threadIdx.x;
    const float* S = blockIdx.y ? U : W;
    __half* D = blockIdx.y ? Up : Wp;
    int pr = idx >> 6;
    int k0 = (idx & 63) * 8;
    int jt = pr / 96;
    int q  = pr - jt * 96;
    int half_ = q / 48;
    int q2 = q - half_ * 48;
    int g  = q2 >> 4;
    int nn = q2 & 15;
    int col = g * 512 + jt * 32 + half_ * 16 + nn;
    __align__(16) __half hi[8], lo[8];
#pragma unroll
    for (int i = 0; i < 8; ++i) {
        float v = S[(size_t)(k0 + i) * 1536 + col];
        __half h = __float2half_rn(v);
        hi[i] = h;
        lo[i] = __float2half_rn(v - __half2float(h));
    }
    *(uint4*)(D + (size_t)pr * 1024 + k0)       = *(const uint4*)hi;
    *(uint4*)(D + (size_t)pr * 1024 + 512 + k0) = *(const uint4*)lo;
}

__global__ __launch_bounds__(256) void pack_x16(const float* __restrict__ x, __half* __restrict__ Xp) {
    unsigned idx = blockIdx.x * 256 + threadIdx.x;
    unsigned t   = idx >> 18;
    unsigned rem = idx & 0x3FFFFu;
    unsigned m   = rem >> 6;
    unsigned k0  = (rem & 63) * 8;
    unsigned bb  = m >> 5, kk = m & 31;
    const float* src = x + ((size_t)bb * T_ + (size_t)(t * SKIP_ + kk)) * 512 + k0;
    float4 v0 = *(const float4*)(src);
    float4 v1 = *(const float4*)(src + 4);
    float f[8] = {v0.x, v0.y, v0.z, v0.w, v1.x, v1.y, v1.z, v1.w};
    __align__(16) __half hi[8];
#pragma unroll
    for (int i = 0; i < 8; ++i) hi[i] = __float2half_rn(f[i]);
    __half* dst = Xp + ((size_t)t * 4096 + m) * 512;
    *(uint4*)(dst + k0) = *(const uint4*)hi;
}

// ---------------- loader (KC=32 stage: 1280 x 16B chunks, 5 per thread) ----------------
__device__ __forceinline__ void load_stage(uint32_t stg, const __half* __restrict__ Arow,
                                           const __half* __restrict__ Bm, int jt, int k0, int tid) {
#pragma unroll
    for (int i = 0; i < 5; ++i) {
        int cc = tid + i * 256;
        if (cc < 512) {
            int row = cc >> 2;
            int c   = cc & 3;
            cp_async16(stg + row * ROWB + c * 16, Arow + (size_t)row * 512 + k0 + c * 8);
        } else {
            int b    = cc - 512;
            int hilo = (b >= 384) ? 1 : 0;
            int idx  = b - hilo * 384;
            int row  = idx >> 2;
            int c    = idx & 3;
            cp_async16(stg + OFF_B + hilo * 7680 + row * ROWB + c * 16,
                       Bm + (size_t)(jt * 96 + row) * 1024 + hilo * 512 + k0 + c * 8);
        }
    }
}

// ---------------- dual-role fused GEMM (2-term: Ahi*(Bhi+Blo)) ----------------
__global__ __launch_bounds__(256, 3) void gemm3(
    const __half* __restrict__ Xp,
    const __half* __restrict__ Wp,
    const __half* __restrict__ Up,
    float* __restrict__ XPf,
    const float* __restrict__ bias,
    const __half* __restrict__ hpack_in,
    const float* __restrict__ hprev,
    float* __restrict__ hout,
    __half* __restrict__ hpk,
    int t, int xp_slot, int xp_only, int first)
{
    extern __shared__ __align__(16) char smem[];
    uint32_t sb = smem_u32(smem);
    const int tid  = threadIdx.x;
    const int lane = tid & 31;
    const int wid  = tid >> 5;
    const int wm   = wid >> 1;
    const int wn   = wid & 1;
    const int jt   = blockIdx.x;
    const int mt   = blockIdx.y;
    const int role = xp_only ? 1 : (int)blockIdx.z;

    float d[2][6][4];
#pragma unroll
    for (int a = 0; a < 2; ++a)
#pragma unroll
        for (int b = 0; b < 6; ++b)
#pragma unroll
            for (int c = 0; c < 4; ++c) d[a][b][c] = 0.f;

    const int do_gemm = (role == 1) || !first;
    if (do_gemm) {
        const __half* A  = (role == 1) ? (Xp + (size_t)xp_slot * 4096u * 512u) : hpack_in;
        const __half* Bm = (role == 1) ? Wp : Up;
        const __half* Arow = A + (size_t)mt * 128 * 512;

        load_stage(sb, Arow, Bm, jt, 0, tid);
        cp_commit();
        load_stage(sb + STAGE_BYTES, Arow, Bm, jt, 32, tid);
        cp_commit();

        const uint32_t aoff = (uint32_t)((wm * 32 + (lane & 15)) * ROWB + (lane >> 4) * 16);
        const uint32_t boff = (uint32_t)((wn * 48 + (lane & 7) + ((lane >> 4) << 3)) * ROWB + ((lane >> 3) & 1) * 16);

        int bufi = 0;   // s % 3
#pragma unroll 1
        for (int s = 0; s < 16; ++s) {
            if (s < 15) cp_wait<1>(); else cp_wait<0>();
            __syncthreads();
            if (s + 2 < 16) {
                int nb = bufi + 2; if (nb >= 3) nb -= 3;
                load_stage(sb + nb * STAGE_BYTES, Arow, Bm, jt, (s + 2) * 32, tid);
                cp_commit();
            }
            uint32_t stg = sb + bufi * STAGE_BYTES;
#pragma unroll
            for (int k16 = 0; k16 < 2; ++k16) {
                uint32_t ah = stg + aoff + k16 * 32;
                uint32_t bb = stg + OFF_B + boff + k16 * 32;
                uint32_t ahi[2][4], bf[3][4];
                ldm4(ah, ahi[0]);  ldm4(ah + 16 * ROWB, ahi[1]);
                // ---- B hi ----
                ldm4(bb, bf[0]);  ldm4(bb + 16 * ROWB, bf[1]);  ldm4(bb + 32 * ROWB, bf[2]);
#pragma unroll
                for (int mi = 0; mi < 2; ++mi)
#pragma unroll
                    for (int nj = 0; nj < 6; ++nj)
                        mma16816(d[mi][nj], ahi[mi], &bf[nj >> 1][(nj & 1) * 2]);
                // ---- B lo (reuse fragment regs) ----
                uint32_t bl = bb + 96 * ROWB;
                ldm4(bl, bf[0]);  ldm4(bl + 16 * ROWB, bf[1]);  ldm4(bl + 32 * ROWB, bf[2]);
#pragma unroll
                for (int mi = 0; mi < 2; ++mi)
#pragma unroll
                    for (int nj = 0; nj < 6; ++nj)
                        mma16816(d[mi][nj], ahi[mi], &bf[nj >> 1][(nj & 1) * 2]);
            }
            if (++bufi >= 3) bufi = 0;
        }
    }

    // ---------------- epilogues ----------------
    if (role == 1) {
        float* xpOut = XPf + (size_t)xp_slot * 4096u * 1536u;
#pragma unroll
        for (int mi = 0; mi < 2; ++mi)
#pragma unroll
            for (int rh = 0; rh < 2; ++rh) {
                int mg = mt * 128 + wm * 32 + mi * 16 + (lane >> 2) + rh * 8;
#pragma unroll
                for (int nj = 0; nj < 6; ++nj) {
                    size_t pc = (size_t)mg * 1536 + jt * 96 + wn * 48 + nj * 8 + (lane & 3) * 2;
                    *(float2*)(xpOut + pc) = make_float2(d[mi][nj][rh * 2], d[mi][nj][rh * 2 + 1]);
                }
            }
    } else {
        const float* xpIn = XPf + (size_t)t * 4096u * 1536u;
#pragma unroll
        for (int mi = 0; mi < 2; ++mi)
#pragma unroll
            for (int rh = 0; rh < 2; ++rh) {
                int mg = mt * 128 + wm * 32 + mi * 16 + (lane >> 2) + rh * 8;
#pragma unroll
                for (int nj = 0; nj < 2; ++nj) {
                    int cb   = nj * 8 + (lane & 3) * 2;
                    int colh = jt * 32 + wn * 16 + cb;
                    size_t pcz = (size_t)mg * 1536 + jt * 96 + wn * 48 + cb;
                    float2 xz = *(const float2*)(xpIn + pcz);
                    float2 xr = *(const float2*)(xpIn + pcz + 16);
                    float2 xh = *(const float2*)(xpIn + pcz + 32);
                    float2 hp = make_float2(0.f, 0.f);
                    if (!first) hp = *(const float2*)(hprev + (size_t)mg * 512 + colh);
                    float2 b0z = *(const float2*)(bias + colh);
                    float2 b1z = *(const float2*)(bias + 1536 + colh);
                    float2 b0r = *(const float2*)(bias + 512 + colh);
                    float2 b1r = *(const float2*)(bias + 2048 + colh);
                    float2 b0h = *(const float2*)(bias + 1024 + colh);
                    float2 b1h = *(const float2*)(bias + 2560 + colh);
                    float xzv[2] = {xz.x, xz.y}, xrv[2] = {xr.x, xr.y}, xhv[2] = {xh.x, xh.y};
                    float hpv[2] = {hp.x, hp.y};
                    float b0zv[2] = {b0z.x, b0z.y}, b1zv[2] = {b1z.x, b1z.y};
                    float b0rv[2] = {b0r.x, b0r.y}, b1rv[2] = {b1r.x, b1r.y};
                    float b0hv[2] = {b0h.x, b0h.y}, b1hv[2] = {b1h.x, b1h.y};
                    float hn[2];
#pragma unroll
                    for (int cc = 0; cc < 2; ++cc) {
                        int r = rh * 2 + cc;
                        float zp  = d[mi][nj][r]     + xzv[cc] + b0zv[cc] + b1zv[cc];
                        float rp  = d[mi][nj + 2][r] + xrv[cc] + b0rv[cc] + b1rv[cc];
                        float xhp = xhv[cc] + b0hv[cc];
                        float rhp = d[mi][nj + 4][r] + b1hv[cc];
                        float z  = sigmoidf_(zp);
                        float rg = sigmoidf_(rp);
                        float hh = fmaxf(xhp + rg * rhp, 0.f);
                        hn[cc] = z * hpv[cc] + (1.f - z) * hh;
                    }
                    *(float2*)(hout + (size_t)mg * 512 + colh) = make_float2(hn[0], hn[1]);
                    *(__half2*)(hpk + (size_t)mg * 512 + colh) =
                        __halves2half2(__float2half_rn(hn[0]), __float2half_rn(hn[1]));
                }
            }
    }
}

// ---------------- host ----------------
extern "C" void kernel_launch(void* const* d_in, const int* in_sizes, int n_in,
                              void* d_out, int out_size) {
    const float* x = (const float*)d_in[0];
    const float* W = (const float*)d_in[1];
    const float* U = (const float*)d_in[2];
    const float* b = (const float*)d_in[3];
    float* out = (float*)d_out;

    __half *Xp, *Wp, *Up, *Hp0;
    float *XPf, *Hf0;
    cudaGetSymbolAddress((void**)&Xp, g_xp16);
    cudaGetSymbolAddress((void**)&Wp, g_wp16);
    cudaGetSymbolAddress((void**)&Up, g_up16);
    cudaGetSymbolAddress((void**)&XPf, g_xpf);
    cudaGetSymbolAddress((void**)&Hf0, g_hf);
    cudaGetSymbolAddress((void**)&Hp0, g_hp16);
    float*  Hf[2] = {Hf0, Hf0 + (size_t)NSEQ * 512};
    __half* Hp[2] = {Hp0, Hp0 + (size_t)NSEQ * 512};

    static int smem_set = 0;
    if (!smem_set) {
        cudaFuncSetAttribute(gemm3, cudaFuncAttributeMaxDynamicSharedMemorySize, SMEM_BYTES);
        smem_set = 1;
    }

    pack_wu16<<<dim3(384, 2), 256>>>(W, U, Wp, Up);
    pack_x16<<<16384, 256>>>(x, Xp);

    // Prelaunch: XP[0] only
    gemm3<<<dim3(16, 32, 1), 256, SMEM_BYTES>>>(Xp, Wp, Up, XPf, b,
                                                nullptr, nullptr, nullptr, nullptr,
                                                0, 0, 1, 0);

    for (int t = 0; t < PT_; ++t) {
        const __half* Ahp  = Hp[(t + 1) & 1];
        const float* hprev = Hf[(t + 1) & 1];
        float* ho = (t == PT_ - 1) ? out : Hf[t & 1];
        const int has_xp = (t < PT_ - 1);
        gemm3<<<dim3(16, 32, has_xp ? 2 : 1), 256, SMEM_BYTES>>>(
            Xp, Wp, Up, XPf, b, Ahp, hprev, ho, Hp[t & 1],
            t, t + 1, 0, t == 0 ? 1 : 0);
    }
    (void)in_sizes; (void)n_in; (void)out_size;
}

// round 9
// speedup vs baseline: 1.0004x; 1.0004x over previous
#include <cuda_runtime.h>
#include <cuda_fp16.h>
#include <cstdint>
#include <math.h>

// ---------------- problem constants ----------------
#define B_    128
#define T_    512
#define PT_   16
#define SKIP_ 32
#define NSEQ  4096

// ---------------- device-global scratch ----------------
__device__ __half g_xp16[16u * 4096u * 512u];    // x packed fp16 (hi only)
__device__ __half g_wp16[1536u * 1024u];         // W packed hi|lo (gate-interleaved cols)
__device__ __half g_up16[1536u * 1024u];         // U packed hi|lo
__device__ float  g_hf[2][NSEQ * 512u];          // hidden fp32 ping-pong
__device__ __half g_hp16[2][NSEQ * 512u];        // hidden fp16 ping-pong

// ---------------- smem layout (per stage, KC=64, rows padded 128B->144B) ----------------
// A: 128 rows * 144 = 18432 ; Bhi: 96 * 144 = 13824 ; Blo: 13824
#define ROWB        144
#define OFF_BHI     18432
#define OFF_BLO     32256
#define STAGE_BYTES 46080
#define SMEM_BYTES  (2 * STAGE_BYTES)    // 92160

// ---------------- helpers ----------------
__device__ __forceinline__ uint32_t smem_u32(const void* p) {
    uint32_t a;
    asm("{ .reg .u64 t; cvta.to.shared.u64 t, %1; cvt.u32.u64 %0, t; }" : "=r"(a) : "l"(p));
    return a;
}
__device__ __forceinline__ void cp_async16(uint32_t s, const void* g) {
    asm volatile("cp.async.cg.shared.global [%0], [%1], 16;" :: "r"(s), "l"(g) : "memory");
}
__device__ __forceinline__ void cp_commit() { asm volatile("cp.async.commit_group;" ::: "memory"); }
template <int N> __device__ __forceinline__ void cp_wait() { asm volatile("cp.async.wait_group %0;" :: "n"(N) : "memory"); }

__device__ __forceinline__ void ldm4(uint32_t addr, uint32_t* r) {
    asm volatile("ldmatrix.sync.aligned.m8n8.x4.shared.b16 {%0,%1,%2,%3}, [%4];"
                 : "=r"(r[0]), "=r"(r[1]), "=r"(r[2]), "=r"(r[3]) : "r"(addr));
}
__device__ __forceinline__ void mma16816(float* d, const uint32_t* a, const uint32_t* b) {
    asm volatile("mma.sync.aligned.m16n8k16.row.col.f32.f16.f16.f32 "
                 "{%0,%1,%2,%3},{%4,%5,%6,%7},{%8,%9},{%0,%1,%2,%3};"
                 : "+f"(d[0]), "+f"(d[1]), "+f"(d[2]), "+f"(d[3])
                 : "r"(a[0]), "r"(a[1]), "r"(a[2]), "r"(a[3]), "r"(b[0]), "r"(b[1]));
}
__device__ __forceinline__ float sigmoidf_(float x) { return 1.f / (1.f + __expf(-x)); }

// ---------------- pack kernels ----------------
// packed B row pr = jt*96 + half*48 + g*16 + nn  ->  natural col g*512 + jt*32 + half*16 + nn
__global__ __launch_bounds__(256) void pack_wu16(const float* __restrict__ W, const float* __restrict__ U,
                                                 __half* __restrict__ Wp, __half* __restrict__ Up) {
    int idx = blockIdx.x * 256 + threadIdx.x;
    const float* S = blockIdx.y ? U : W;
    __half* D = blockIdx.y ? Up : Wp;
    int pr = idx >> 6;
    int k0 = (idx & 63) * 8;
    int jt = pr / 96;
    int q  = pr - jt * 96;
    int half_ = q / 48;
    int q2 = q - half_ * 48;
    int g  = q2 >> 4;
    int nn = q2 & 15;
    int col = g * 512 + jt * 32 + half_ * 16 + nn;
    __align__(16) __half hi[8], lo[8];
#pragma unroll
    for (int i = 0; i < 8; ++i) {
        float v = S[(size_t)(k0 + i) * 1536 + col];
        __half h = __float2half_rn(v);
        hi[i] = h;
        lo[i] = __float2half_rn(v - __half2float(h));
    }
    *(uint4*)(D + (size_t)pr * 1024 + k0)       = *(const uint4*)hi;
    *(uint4*)(D + (size_t)pr * 1024 + 512 + k0) = *(const uint4*)lo;
}

__global__ __launch_bounds__(256) void pack_x16(const float* __restrict__ x, __half* __restrict__ Xp) {
    unsigned idx = blockIdx.x * 256 + threadIdx.x;
    unsigned t   = idx >> 18;
    unsigned rem = idx & 0x3FFFFu;
    unsigned m   = rem >> 6;
    unsigned k0  = (rem & 63) * 8;
    unsigned bb  = m >> 5, kk = m & 31;
    const float* src = x + ((size_t)bb * T_ + (size_t)(t * SKIP_ + kk)) * 512 + k0;
    float4 v0 = *(const float4*)(src);
    float4 v1 = *(const float4*)(src + 4);
    float f[8] = {v0.x, v0.y, v0.z, v0.w, v1.x, v1.y, v1.z, v1.w};
    __align__(16) __half hi[8];
#pragma unroll
    for (int i = 0; i < 8; ++i) hi[i] = __float2half_rn(f[i]);
    __half* dst = Xp + ((size_t)t * 4096 + m) * 512;
    *(uint4*)(dst + k0) = *(const uint4*)hi;
}

// ---------------- loader (KC=64 stage) ----------------
__device__ __forceinline__ void load_stage(uint32_t stg, const __half* __restrict__ Arow,
                                           const __half* __restrict__ Bm, int jt, int k0, int tid) {
    // A (hi only): 128 rows x 8 chunks = 1024
#pragma unroll
    for (int i = 0; i < 4; ++i) {
        int a = tid + i * 256;
        int row = a >> 3;
        int c   = a & 7;
        cp_async16(stg + row * ROWB + c * 16, Arow + (size_t)row * 512 + k0 + c * 8);
    }
    // B hi+lo: 2 x 96 rows x 8 chunks = 1536
#pragma unroll
    for (int i = 0; i < 6; ++i) {
        int b = tid + i * 256;
        int hilo = (b >= 768) ? 1 : 0;
        int idx  = b - hilo * 768;
        int row  = idx >> 3;
        int c    = idx & 7;
        cp_async16(stg + OFF_BHI + hilo * (OFF_BLO - OFF_BHI) + row * ROWB + c * 16,
                   Bm + (size_t)(jt * 96 + row) * 1024 + hilo * 512 + k0 + c * 8);
    }
}

// ---------------- fully fused GRU step ----------------
// K=1024 accumulation: stages 0..7 = x_t@W (dz,dr,dxh), stages 8..15 = h@U (dz,dr,drh).
// Gate epilogue directly from register accumulators; no XP tensor.
__global__ __launch_bounds__(256, 2) void gru_fused(
    const __half* __restrict__ Xt,       // x packed for this t: [4096][512]
    const __half* __restrict__ Wp,
    const __half* __restrict__ Up,
    const float* __restrict__ bias,
    const __half* __restrict__ hpack_in,
    const float* __restrict__ hprev,
    float* __restrict__ hout,
    __half* __restrict__ hpk,
    int first, int last)
{
    extern __shared__ __align__(16) char smem[];
    uint32_t sb = smem_u32(smem);
    const int tid  = threadIdx.x;
    const int lane = tid & 31;
    const int wid  = tid >> 5;
    const int wm   = wid >> 1;
    const int wn   = wid & 1;
    const int jt   = blockIdx.x;
    const int mt   = blockIdx.y;

    float dz[2][2][4], dr[2][2][4], dxh[2][2][4], drh[2][2][4];
#pragma unroll
    for (int a = 0; a < 2; ++a)
#pragma unroll
        for (int b = 0; b < 2; ++b)
#pragma unroll
            for (int c = 0; c < 4; ++c) {
                dz[a][b][c] = 0.f; dr[a][b][c] = 0.f;
                dxh[a][b][c] = 0.f; drh[a][b][c] = 0.f;
            }

    const int S = first ? 8 : 16;
    const __half* ArowX = Xt + (size_t)mt * 128 * 512;
    const __half* ArowH = hpack_in + (size_t)mt * 128 * 512;

    load_stage(sb, ArowX, Wp, jt, 0, tid);
    cp_commit();

    const uint32_t aoff = (uint32_t)((wm * 32 + (lane & 15)) * ROWB + (lane >> 4) * 16);
    const uint32_t boff = (uint32_t)((wn * 48 + (lane & 7) + ((lane >> 4) << 3)) * ROWB + ((lane >> 3) & 1) * 16);

#pragma unroll 1
    for (int s = 0; s < S; ++s) {
        if (s < S - 1) {
            int sn = s + 1;
            const __half* An = (sn < 8) ? ArowX : ArowH;
            const __half* Bn = (sn < 8) ? Wp : Up;
            load_stage(sb + (sn & 1) * STAGE_BYTES, An, Bn, jt, (sn & 7) * 64, tid);
            cp_commit();
            cp_wait<1>();
        } else {
            cp_wait<0>();
        }
        __syncthreads();
        uint32_t stg = sb + (s & 1) * STAGE_BYTES;
        const bool ph0 = (s < 8);
#pragma unroll
        for (int k16 = 0; k16 < 4; ++k16) {
            uint32_t ah = stg + aoff + k16 * 32;
            uint32_t bh = stg + OFF_BHI + boff + k16 * 32;
            uint32_t bl = stg + OFF_BLO + boff + k16 * 32;
            uint32_t A2[2][4], BH[3][4], BL[3][4];
            ldm4(ah, A2[0]);  ldm4(ah + 16 * ROWB, A2[1]);
            ldm4(bh, BH[0]);  ldm4(bh + 16 * ROWB, BH[1]);  ldm4(bh + 32 * ROWB, BH[2]);
            ldm4(bl, BL[0]);  ldm4(bl + 16 * ROWB, BL[1]);  ldm4(bl + 32 * ROWB, BL[2]);
#pragma unroll
            for (int mi = 0; mi < 2; ++mi)
#pragma unroll
                for (int nj = 0; nj < 2; ++nj) {
                    mma16816(dz[mi][nj], A2[mi], &BH[0][nj * 2]);
                    mma16816(dz[mi][nj], A2[mi], &BL[0][nj * 2]);
                    mma16816(dr[mi][nj], A2[mi], &BH[1][nj * 2]);
                    mma16816(dr[mi][nj], A2[mi], &BL[1][nj * 2]);
                }
            if (ph0) {
#pragma unroll
                for (int mi = 0; mi < 2; ++mi)
#pragma unroll
                    for (int nj = 0; nj < 2; ++nj) {
                        mma16816(dxh[mi][nj], A2[mi], &BH[2][nj * 2]);
                        mma16816(dxh[mi][nj], A2[mi], &BL[2][nj * 2]);
                    }
            } else {
#pragma unroll
                for (int mi = 0; mi < 2; ++mi)
#pragma unroll
                    for (int nj = 0; nj < 2; ++nj) {
                        mma16816(drh[mi][nj], A2[mi], &BH[2][nj * 2]);
                        mma16816(drh[mi][nj], A2[mi], &BL[2][nj * 2]);
                    }
            }
        }
        __syncthreads();
    }

    // ---------------- gate epilogue (direct from registers) ----------------
#pragma unroll
    for (int mi = 0; mi < 2; ++mi)
#pragma unroll
        for (int rh = 0; rh < 2; ++rh) {
            int mg = mt * 128 + wm * 32 + mi * 16 + (lane >> 2) + rh * 8;
#pragma unroll
            for (int nj = 0; nj < 2; ++nj) {
                int cb   = nj * 8 + (lane & 3) * 2;
                int colh = jt * 32 + wn * 16 + cb;
                float2 hp = make_float2(0.f, 0.f);
                if (!first) hp = *(const float2*)(hprev + (size_t)mg * 512 + colh);
                float2 b0z = *(const float2*)(bias + colh);
                float2 b1z = *(const float2*)(bias + 1536 + colh);
                float2 b0r = *(const float2*)(bias + 512 + colh);
                float2 b1r = *(const float2*)(bias + 2048 + colh);
                float2 b0h = *(const float2*)(bias + 1024 + colh);
                float2 b1h = *(const float2*)(bias + 2560 + colh);
                float hpv[2] = {hp.x, hp.y};
                float b0zv[2] = {b0z.x, b0z.y}, b1zv[2] = {b1z.x, b1z.y};
                float b0rv[2] = {b0r.x, b0r.y}, b1rv[2] = {b1r.x, b1r.y};
                float b0hv[2] = {b0h.x, b0h.y}, b1hv[2] = {b1h.x, b1h.y};
                float hn[2];
#pragma unroll
                for (int cc = 0; cc < 2; ++cc) {
                    int r = rh * 2 + cc;
                    float zp  = dz[mi][nj][r] + b0zv[cc] + b1zv[cc];
                    float rp  = dr[mi][nj][r] + b0rv[cc] + b1rv[cc];
                    float xhp = dxh[mi][nj][r] + b0hv[cc];
                    float rhp = drh[mi][nj][r] + b1hv[cc];
                    float z  = sigmoidf_(zp);
                    float rg = sigmoidf_(rp);
                    float hh = fmaxf(xhp + rg * rhp, 0.f);
                    hn[cc] = z * hpv[cc] + (1.f - z) * hh;
                }
                *(float2*)(hout + (size_t)mg * 512 + colh) = make_float2(hn[0], hn[1]);
                if (!last)
                    *(__half2*)(hpk + (size_t)mg * 512 + colh) =
                        __halves2half2(__float2half_rn(hn[0]), __float2half_rn(hn[1]));
            }
        }
}

// ---------------- host ----------------
extern "C" void kernel_launch(void* const* d_in, const int* in_sizes, int n_in,
                              void* d_out, int out_size) {
    const float* x = (const float*)d_in[0];
    const float* W = (const float*)d_in[1];
    const float* U = (const float*)d_in[2];
    const float* b = (const float*)d_in[3];
    float* out = (float*)d_out;

    __half *Xp, *Wp, *Up, *Hp0;
    float *Hf0;
    cudaGetSymbolAddress((void**)&Xp, g_xp16);
    cudaGetSymbolAddress((void**)&Wp, g_wp16);
    cudaGetSymbolAddress((void**)&Up, g_up16);
    cudaGetSymbolAddress((void**)&Hf0, g_hf);
    cudaGetSymbolAddress((void**)&Hp0, g_hp16);
    float*  Hf[2] = {Hf0, Hf0 + (size_t)NSEQ * 512};
    __half* Hp[2] = {Hp0, Hp0 + (size_t)NSEQ * 512};

    static int smem_set = 0;
    if (!smem_set) {
        cudaFuncSetAttribute(gru_fused, cudaFuncAttributeMaxDynamicSharedMemorySize, SMEM_BYTES);
        smem_set = 1;
    }

    pack_wu16<<<dim3(384, 2), 256>>>(W, U, Wp, Up);
    pack_x16<<<16384, 256>>>(x, Xp);

    for (int t = 0; t < PT_; ++t) {
        const __half* Xt   = Xp + (size_t)t * 4096u * 512u;
        const __half* Ahp  = Hp[(t + 1) & 1];
        const float* hprev = Hf[(t + 1) & 1];
        float* ho = (t == PT_ - 1) ? out : Hf[t & 1];
        gru_fused<<<dim3(16, 32), 256, SMEM_BYTES>>>(
            Xt, Wp, Up, b, Ahp, hprev, ho, Hp[t & 1],
            t == 0 ? 1 : 0, t == PT_ - 1 ? 1 : 0);
    }
    (void)in_sizes; (void)n_in; (void)out_size;
}

// round 10
// speedup vs baseline: 1.0095x; 1.0091x over previous
#include <cuda_runtime.h>
#include <cuda_fp16.h>
#include <cstdint>
#include <math.h>

// ---------------- problem constants ----------------
#define B_    128
#define T_    512
#define PT_   16
#define SKIP_ 32
#define NSEQ  4096

// ---------------- device-global scratch ----------------
__device__ __half g_xp16[16u * 4096u * 512u];    // x packed fp16 (hi only)
__device__ __half g_wp16[1536u * 1024u];         // W packed hi|lo (gate-interleaved cols)
__device__ __half g_up16[1536u * 1024u];         // U packed hi|lo
__device__ float  g_hf[2][NSEQ * 512u];          // hidden fp32 ping-pong
__device__ __half g_hp16[2][NSEQ * 512u];        // hidden fp16 ping-pong

// ---------------- smem layout (per stage, KC=64, rows padded 128B->144B) ----------------
#define ROWB        144
#define OFF_BHI     18432
#define OFF_BLO     32256
#define STAGE_BYTES 46080
#define SMEM_BYTES  (2 * STAGE_BYTES)    // 92160

// ---------------- helpers ----------------
__device__ __forceinline__ uint32_t smem_u32(const void* p) {
    uint32_t a;
    asm("{ .reg .u64 t; cvta.to.shared.u64 t, %1; cvt.u32.u64 %0, t; }" : "=r"(a) : "l"(p));
    return a;
}
__device__ __forceinline__ void cp_async16(uint32_t s, const void* g) {
    asm volatile("cp.async.cg.shared.global [%0], [%1], 16;" :: "r"(s), "l"(g) : "memory");
}
__device__ __forceinline__ void cp_commit() { asm volatile("cp.async.commit_group;" ::: "memory"); }
template <int N> __device__ __forceinline__ void cp_wait() { asm volatile("cp.async.wait_group %0;" :: "n"(N) : "memory"); }

__device__ __forceinline__ void ldm4(uint32_t addr, uint32_t* r) {
    asm volatile("ldmatrix.sync.aligned.m8n8.x4.shared.b16 {%0,%1,%2,%3}, [%4];"
                 : "=r"(r[0]), "=r"(r[1]), "=r"(r[2]), "=r"(r[3]) : "r"(addr));
}
__device__ __forceinline__ void mma16816(float* d, const uint32_t* a, const uint32_t* b) {
    asm volatile("mma.sync.aligned.m16n8k16.row.col.f32.f16.f16.f32 "
                 "{%0,%1,%2,%3},{%4,%5,%6,%7},{%8,%9},{%0,%1,%2,%3};"
                 : "+f"(d[0]), "+f"(d[1]), "+f"(d[2]), "+f"(d[3])
                 : "r"(a[0]), "r"(a[1]), "r"(a[2]), "r"(a[3]), "r"(b[0]), "r"(b[1]));
}
__device__ __forceinline__ float sigmoidf_(float x) { return 1.f / (1.f + __expf(-x)); }

// ---------------- pack kernels ----------------
__global__ __launch_bounds__(256) void pack_wu16(const float* __restrict__ W, const float* __restrict__ U,
                                                 __half* __restrict__ Wp, __half* __restrict__ Up) {
    int idx = blockIdx.x * 256 + threadIdx.x;
    const float* S = blockIdx.y ? U : W;
    __half* D = blockIdx.y ? Up : Wp;
    int pr = idx >> 6;
    int k0 = (idx & 63) * 8;
    int jt = pr / 96;
    int q  = pr - jt * 96;
    int half_ = q / 48;
    int q2 = q - half_ * 48;
    int g  = q2 >> 4;
    int nn = q2 & 15;
    int col = g * 512 + jt * 32 + half_ * 16 + nn;
    __align__(16) __half hi[8], lo[8];
#pragma unroll
    for (int i = 0; i < 8; ++i) {
        float v = S[(size_t)(k0 + i) * 1536 + col];
        __half h = __float2half_rn(v);
        hi[i] = h;
        lo[i] = __float2half_rn(v - __half2float(h));
    }
    *(uint4*)(D + (size_t)pr * 1024 + k0)       = *(const uint4*)hi;
    *(uint4*)(D + (size_t)pr * 1024 + 512 + k0) = *(const uint4*)lo;
}

__global__ __launch_bounds__(256) void pack_x16(const float* __restrict__ x, __half* __restrict__ Xp) {
    unsigned idx = blockIdx.x * 256 + threadIdx.x;
    unsigned t   = idx >> 18;
    unsigned rem = idx & 0x3FFFFu;
    unsigned m   = rem >> 6;
    unsigned k0  = (rem & 63) * 8;
    unsigned bb  = m >> 5, kk = m & 31;
    const float* src = x + ((size_t)bb * T_ + (size_t)(t * SKIP_ + kk)) * 512 + k0;
    float4 v0 = *(const float4*)(src);
    float4 v1 = *(const float4*)(src + 4);
    float f[8] = {v0.x, v0.y, v0.z, v0.w, v1.x, v1.y, v1.z, v1.w};
    __align__(16) __half hi[8];
#pragma unroll
    for (int i = 0; i < 8; ++i) hi[i] = __float2half_rn(f[i]);
    __half* dst = Xp + ((size_t)t * 4096 + m) * 512;
    *(uint4*)(dst + k0) = *(const uint4*)hi;
}

// ---------------- loader (KC=64 stage) ----------------
__device__ __forceinline__ void load_stage(uint32_t stg, const __half* __restrict__ Arow,
                                           const __half* __restrict__ Bm, int jt, int k0, int tid) {
#pragma unroll
    for (int i = 0; i < 4; ++i) {
        int a = tid + i * 256;
        int row = a >> 3;
        int c   = a & 7;
        cp_async16(stg + row * ROWB + c * 16, Arow + (size_t)row * 512 + k0 + c * 8);
    }
#pragma unroll
    for (int i = 0; i < 6; ++i) {
        int b = tid + i * 256;
        int hilo = (b >= 768) ? 1 : 0;
        int idx  = b - hilo * 768;
        int row  = idx >> 3;
        int c    = idx & 7;
        cp_async16(stg + OFF_BHI + hilo * (OFF_BLO - OFF_BHI) + row * ROWB + c * 16,
                   Bm + (size_t)(jt * 96 + row) * 1024 + hilo * 512 + k0 + c * 8);
    }
}

// 12 independent-accumulator MMAs for one B term (BH or BL)
#define DO_TERM(BT, HACC)                                              \
    do {                                                               \
        _Pragma("unroll")                                              \
        for (int mi = 0; mi < 2; ++mi)                                 \
            _Pragma("unroll")                                          \
            for (int nj = 0; nj < 2; ++nj)                             \
                mma16816(dz[mi][nj], A2[mi], &BT[0][nj * 2]);          \
        _Pragma("unroll")                                              \
        for (int mi = 0; mi < 2; ++mi)                                 \
            _Pragma("unroll")                                          \
            for (int nj = 0; nj < 2; ++nj)                             \
                mma16816(dr[mi][nj], A2[mi], &BT[1][nj * 2]);          \
        _Pragma("unroll")                                              \
        for (int mi = 0; mi < 2; ++mi)                                 \
            _Pragma("unroll")                                          \
            for (int nj = 0; nj < 2; ++nj)                             \
                mma16816(HACC[mi][nj], A2[mi], &BT[2][nj * 2]);        \
    } while (0)

// ---------------- fully fused GRU step ----------------
// K=1024: stages 0..7 = x_t@W (dz,dr,dxh), stages 8..15 = h@U (dz,dr,drh).
__global__ __launch_bounds__(256, 2) void gru_fused(
    const __half* __restrict__ Xt,
    const __half* __restrict__ Wp,
    const __half* __restrict__ Up,
    const float* __restrict__ bias,
    const __half* __restrict__ hpack_in,
    const float* __restrict__ hprev,
    float* __restrict__ hout,
    __half* __restrict__ hpk,
    int first, int last)
{
    extern __shared__ __align__(16) char smem[];
    uint32_t sb = smem_u32(smem);
    const int tid  = threadIdx.x;
    const int lane = tid & 31;
    const int wid  = tid >> 5;
    const int wm   = wid >> 1;
    const int wn   = wid & 1;
    const int jt   = blockIdx.x;
    const int mt   = blockIdx.y;

    float dz[2][2][4], dr[2][2][4], dxh[2][2][4], drh[2][2][4];
#pragma unroll
    for (int a = 0; a < 2; ++a)
#pragma unroll
        for (int b = 0; b < 2; ++b)
#pragma unroll
            for (int c = 0; c < 4; ++c) {
                dz[a][b][c] = 0.f; dr[a][b][c] = 0.f;
                dxh[a][b][c] = 0.f; drh[a][b][c] = 0.f;
            }

    const int S = first ? 8 : 16;
    const __half* ArowX = Xt + (size_t)mt * 128 * 512;
    const __half* ArowH = hpack_in + (size_t)mt * 128 * 512;

    load_stage(sb, ArowX, Wp, jt, 0, tid);
    cp_commit();

    const uint32_t aoff = (uint32_t)((wm * 32 + (lane & 15)) * ROWB + (lane >> 4) * 16);
    const uint32_t boff = (uint32_t)((wn * 48 + (lane & 7) + ((lane >> 4) << 3)) * ROWB + ((lane >> 3) & 1) * 16);

#pragma unroll 1
    for (int s = 0; s < S; ++s) {
        if (s < S - 1) {
            int sn = s + 1;
            const __half* An = (sn < 8) ? ArowX : ArowH;
            const __half* Bn = (sn < 8) ? Wp : Up;
            load_stage(sb + (sn & 1) * STAGE_BYTES, An, Bn, jt, (sn & 7) * 64, tid);
            cp_commit();
            cp_wait<1>();
        } else {
            cp_wait<0>();
        }
        __syncthreads();
        uint32_t stg = sb + (s & 1) * STAGE_BYTES;
        const bool ph0 = (s < 8);
#pragma unroll
        for (int k16 = 0; k16 < 4; ++k16) {
            uint32_t ah = stg + aoff + k16 * 32;
            uint32_t bh = stg + OFF_BHI + boff + k16 * 32;
            uint32_t bl = stg + OFF_BLO + boff + k16 * 32;
            uint32_t A2[2][4], BH[3][4], BL[3][4];
            ldm4(ah, A2[0]);  ldm4(ah + 16 * ROWB, A2[1]);
            ldm4(bh, BH[0]);  ldm4(bh + 16 * ROWB, BH[1]);  ldm4(bh + 32 * ROWB, BH[2]);
            ldm4(bl, BL[0]);  ldm4(bl + 16 * ROWB, BL[1]);  ldm4(bl + 32 * ROWB, BL[2]);
            if (ph0) {
                DO_TERM(BH, dxh);
                DO_TERM(BL, dxh);
            } else {
                DO_TERM(BH, drh);
                DO_TERM(BL, drh);
            }
        }
        __syncthreads();
    }

    // ---------------- gate epilogue ----------------
#pragma unroll
    for (int mi = 0; mi < 2; ++mi)
#pragma unroll
        for (int rh = 0; rh < 2; ++rh) {
            int mg = mt * 128 + wm * 32 + mi * 16 + (lane >> 2) + rh * 8;
#pragma unroll
            for (int nj = 0; nj < 2; ++nj) {
                int cb   = nj * 8 + (lane & 3) * 2;
                int colh = jt * 32 + wn * 16 + cb;
                float2 hp = make_float2(0.f, 0.f);
                if (!first) hp = *(const float2*)(hprev + (size_t)mg * 512 + colh);
                float2 b0z = *(const float2*)(bias + colh);
                float2 b1z = *(const float2*)(bias + 1536 + colh);
                float2 b0r = *(const float2*)(bias + 512 + colh);
                float2 b1r = *(const float2*)(bias + 2048 + colh);
                float2 b0h = *(const float2*)(bias + 1024 + colh);
                float2 b1h = *(const float2*)(bias + 2560 + colh);
                float hpv[2] = {hp.x, hp.y};
                float b0zv[2] = {b0z.x, b0z.y}, b1zv[2] = {b1z.x, b1z.y};
                float b0rv[2] = {b0r.x, b0r.y}, b1rv[2] = {b1r.x, b1r.y};
                float b0hv[2] = {b0h.x, b0h.y}, b1hv[2] = {b1h.x, b1h.y};
                float hn[2];
#pragma unroll
                for (int cc = 0; cc < 2; ++cc) {
                    int r = rh * 2 + cc;
                    float zp  = dz[mi][nj][r] + b0zv[cc] + b1zv[cc];
                    float rp  = dr[mi][nj][r] + b0rv[cc] + b1rv[cc];
                    float xhp = dxh[mi][nj][r] + b0hv[cc];
                    float rhp = drh[mi][nj][r] + b1hv[cc];
                    float z  = sigmoidf_(zp);
                    float rg = sigmoidf_(rp);
                    float hh = fmaxf(xhp + rg * rhp, 0.f);
                    hn[cc] = z * hpv[cc] + (1.f - z) * hh;
                }
                *(float2*)(hout + (size_t)mg * 512 + colh) = make_float2(hn[0], hn[1]);
                if (!last)
                    *(__half2*)(hpk + (size_t)mg * 512 + colh) =
                        __halves2half2(__float2half_rn(hn[0]), __float2half_rn(hn[1]));
            }
        }
}

// ---------------- host ----------------
extern "C" void kernel_launch(void* const* d_in, const int* in_sizes, int n_in,
                              void* d_out, int out_size) {
    const float* x = (const float*)d_in[0];
    const float* W = (const float*)d_in[1];
    const float* U = (const float*)d_in[2];
    const float* b = (const float*)d_in[3];
    float* out = (float*)d_out;

    __half *Xp, *Wp, *Up, *Hp0;
    float *Hf0;
    cudaGetSymbolAddress((void**)&Xp, g_xp16);
    cudaGetSymbolAddress((void**)&Wp, g_wp16);
    cudaGetSymbolAddress((void**)&Up, g_up16);
    cudaGetSymbolAddress((void**)&Hf0, g_hf);
    cudaGetSymbolAddress((void**)&Hp0, g_hp16);
    float*  Hf[2] = {Hf0, Hf0 + (size_t)NSEQ * 512};
    __half* Hp[2] = {Hp0, Hp0 + (size_t)NSEQ * 512};

    static int smem_set = 0;
    if (!smem_set) {
        cudaFuncSetAttribute(gru_fused, cudaFuncAttributeMaxDynamicSharedMemorySize, SMEM_BYTES);
        smem_set = 1;
    }

    pack_wu16<<<dim3(384, 2), 256>>>(W, U, Wp, Up);
    pack_x16<<<16384, 256>>>(x, Xp);

    for (int t = 0; t < PT_; ++t) {
        const __half* Xt   = Xp + (size_t)t * 4096u * 512u;
        const __half* Ahp  = Hp[(t + 1) & 1];
        const float* hprev = Hf[(t + 1) & 1];
        float* ho = (t == PT_ - 1) ? out : Hf[t & 1];
        gru_fused<<<dim3(16, 32), 256, SMEM_BYTES>>>(
            Xt, Wp, Up, b, Ahp, hprev, ho, Hp[t & 1],
            t == 0 ? 1 : 0, t == PT_ - 1 ? 1 : 0);
    }
    (void)in_sizes; (void)n_in; (void)out_size;
}

// round 13
// speedup vs baseline: 1.0474x; 1.0376x over previous
#include <cuda_runtime.h>
#include <cuda_fp16.h>
#include <cstdint>
#include <math.h>

// ---------------- problem constants ----------------
#define B_    128
#define T_    512
#define PT_   16
#define SKIP_ 32
#define NSEQ  4096

// ---------------- device-global scratch ----------------
__device__ __half g_xp16[16u * 4096u * 512u];    // x packed fp16 (hi only)
__device__ __half g_wp16[1536u * 1024u];         // W packed hi|lo (gate-interleaved cols)
__device__ __half g_up16[1536u * 1024u];         // U packed hi|lo
__device__ float  g_hf[2][NSEQ * 512u];          // hidden fp32 ping-pong
__device__ __half g_hp16[2][NSEQ * 512u];        // hidden fp16 ping-pong

// ---------------- smem layout (per stage, KC=64, rows padded 128B->144B) ----------------
#define ROWB        144
#define OFF_BHI     18432
#define OFF_BLO     32256
#define STAGE_BYTES 46080
#define SMEM_BYTES  (2 * STAGE_BYTES)    // 92160

// ---------------- helpers ----------------
__device__ __forceinline__ uint32_t smem_u32(const void* p) {
    uint32_t a;
    asm("{ .reg .u64 t; cvta.to.shared.u64 t, %1; cvt.u32.u64 %0, t; }" : "=r"(a) : "l"(p));
    return a;
}
__device__ __forceinline__ void cp_async16(uint32_t s, const void* g) {
    asm volatile("cp.async.cg.shared.global [%0], [%1], 16;" :: "r"(s), "l"(g) : "memory");
}
__device__ __forceinline__ void cp_commit() { asm volatile("cp.async.commit_group;" ::: "memory"); }
template <int N> __device__ __forceinline__ void cp_wait() { asm volatile("cp.async.wait_group %0;" :: "n"(N) : "memory"); }

__device__ __forceinline__ void ldm4(uint32_t addr, uint32_t* r) {
    asm volatile("ldmatrix.sync.aligned.m8n8.x4.shared.b16 {%0,%1,%2,%3}, [%4];"
                 : "=r"(r[0]), "=r"(r[1]), "=r"(r[2]), "=r"(r[3]) : "r"(addr));
}
__device__ __forceinline__ void mma16816(float* d, const uint32_t* a, const uint32_t* b) {
    asm volatile("mma.sync.aligned.m16n8k16.row.col.f32.f16.f16.f32 "
                 "{%0,%1,%2,%3},{%4,%5,%6,%7},{%8,%9},{%0,%1,%2,%3};"
                 : "+f"(d[0]), "+f"(d[1]), "+f"(d[2]), "+f"(d[3])
                 : "r"(a[0]), "r"(a[1]), "r"(a[2]), "r"(a[3]), "r"(b[0]), "r"(b[1]));
}
__device__ __forceinline__ float sigmoidf_(float x) { return 1.f / (1.f + __expf(-x)); }

// ---------------- pack kernels ----------------
__global__ __launch_bounds__(256) void pack_wu16(const float* __restrict__ W, const float* __restrict__ U,
                                                 __half* __restrict__ Wp, __half* __restrict__ Up) {
    int idx = blockIdx.x * 256 + threadIdx.x;
    const float* S = blockIdx.y ? U : W;
    __half* D = blockIdx.y ? Up : Wp;
    int pr = idx >> 6;
    int k0 = (idx & 63) * 8;
    int jt = pr / 96;
    int q  = pr - jt * 96;
    int half_ = q / 48;
    int q2 = q - half_ * 48;
    int g  = q2 >> 4;
    int nn = q2 & 15;
    int col = g * 512 + jt * 32 + half_ * 16 + nn;
    __align__(16) __half hi[8], lo[8];
#pragma unroll
    for (int i = 0; i < 8; ++i) {
        float v = S[(size_t)(k0 + i) * 1536 + col];
        __half h = __float2half_rn(v);
        hi[i] = h;
        lo[i] = __float2half_rn(v - __half2float(h));
    }
    *(uint4*)(D + (size_t)pr * 1024 + k0)       = *(const uint4*)hi;
    *(uint4*)(D + (size_t)pr * 1024 + 512 + k0) = *(const uint4*)lo;
}

__global__ __launch_bounds__(256) void pack_x16(const float* __restrict__ x, __half* __restrict__ Xp) {
    unsigned idx = blockIdx.x * 256 + threadIdx.x;
    unsigned t   = idx >> 18;
    unsigned rem = idx & 0x3FFFFu;
    unsigned m   = rem >> 6;
    unsigned k0  = (rem & 63) * 8;
    unsigned bb  = m >> 5, kk = m & 31;
    const float* src = x + ((size_t)bb * T_ + (size_t)(t * SKIP_ + kk)) * 512 + k0;
    float4 v0 = *(const float4*)(src);
    float4 v1 = *(const float4*)(src + 4);
    float f[8] = {v0.x, v0.y, v0.z, v0.w, v1.x, v1.y, v1.z, v1.w};
    __align__(16) __half hi[8];
#pragma unroll
    for (int i = 0; i < 8; ++i) hi[i] = __float2half_rn(f[i]);
    __half* dst = Xp + ((size_t)t * 4096 + m) * 512;
    *(uint4*)(dst + k0) = *(const uint4*)hi;
}

// ---------------- loader (KC=64 stage) ----------------
__device__ __forceinline__ void load_stage(uint32_t stg, const __half* __restrict__ Arow,
                                           const __half* __restrict__ Bm, int jt, int k0, int tid) {
#pragma unroll
    for (int i = 0; i < 4; ++i) {
        int a = tid + i * 256;
        int row = a >> 3;
        int c   = a & 7;
        cp_async16(stg + row * ROWB + c * 16, Arow + (size_t)row * 512 + k0 + c * 8);
    }
#pragma unroll
    for (int i = 0; i < 6; ++i) {
        int b = tid + i * 256;
        int hilo = (b >= 768) ? 1 : 0;
        int idx  = b - hilo * 768;
        int row  = idx >> 3;
        int c    = idx & 7;
        cp_async16(stg + OFF_BHI + hilo * (OFF_BLO - OFF_BHI) + row * ROWB + c * 16,
                   Bm + (size_t)(jt * 96 + row) * 1024 + hilo * 512 + k0 + c * 8);
    }
}

// 12 independent-accumulator MMAs for one B term (BH or BL)
#define DO_TERM(BT, HACC)                                              \
    do {                                                               \
        _Pragma("unroll")                                              \
        for (int mi = 0; mi < 2; ++mi)                                 \
            _Pragma("unroll")                                          \
            for (int nj = 0; nj < 2; ++nj)                             \
                mma16816(dz[mi][nj], A2[mi], &BT[0][nj * 2]);          \
        _Pragma("unroll")                                              \
        for (int mi = 0; mi < 2; ++mi)                                 \
            _Pragma("unroll")                                          \
            for (int nj = 0; nj < 2; ++nj)                             \
                mma16816(dr[mi][nj], A2[mi], &BT[1][nj * 2]);          \
        _Pragma("unroll")                                              \
        for (int mi = 0; mi < 2; ++mi)                                 \
            _Pragma("unroll")                                          \
            for (int nj = 0; nj < 2; ++nj)                             \
                mma16816(HACC[mi][nj], A2[mi], &BT[2][nj * 2]);        \
    } while (0)

// full stage MMA body over one smem buffer (stg), h-gate target HACC
#define STAGE_MMA(HACC)                                                            \
    do {                                                                           \
        _Pragma("unroll")                                                          \
        for (int k16 = 0; k16 < 4; ++k16) {                                        \
            uint32_t ah = stg + aoff + k16 * 32;                                   \
            uint32_t bh = stg + OFF_BHI + boff + k16 * 32;                         \
            uint32_t bl = stg + OFF_BLO + boff + k16 * 32;                         \
            uint32_t A2[2][4], BH[3][4], BL[3][4];                                 \
            ldm4(ah, A2[0]);  ldm4(ah + 16 * ROWB, A2[1]);                         \
            ldm4(bh, BH[0]);  ldm4(bh + 16 * ROWB, BH[1]);  ldm4(bh + 32 * ROWB, BH[2]); \
            ldm4(bl, BL[0]);  ldm4(bl + 16 * ROWB, BL[1]);  ldm4(bl + 32 * ROWB, BL[2]); \
            DO_TERM(BH, HACC);                                                     \
            DO_TERM(BL, HACC);                                                     \
        }                                                                          \
    } while (0)

// ---------------- fully fused GRU step ----------------
// K=1024 in two 8-stage phases (unroll-by-2: parity constant-folds, pointers invariant):
//   phase 0: x_t@W  -> dz, dr, dxh      phase 1: h@U -> dz, dr, drh
__global__ __launch_bounds__(256, 2) void gru_fused(
    const __half* __restrict__ Xt,
    const __half* __restrict__ Wp,
    const __half* __restrict__ Up,
    const float* __restrict__ bias,
    const __half* __restrict__ hpack_in,
    const float* __restrict__ hprev,
    float* __restrict__ hout,
    __half* __restrict__ hpk,
    int first, int last)
{
    extern __shared__ __align__(16) char smem[];
    uint32_t sb = smem_u32(smem);
    const int tid  = threadIdx.x;
    const int lane = tid & 31;
    const int wid  = tid >> 5;
    const int wm   = wid >> 1;
    const int wn   = wid & 1;
    const int jt   = blockIdx.x;
    const int mt   = blockIdx.y;

    float dz[2][2][4], dr[2][2][4], dxh[2][2][4], drh[2][2][4];
#pragma unroll
    for (int a = 0; a < 2; ++a)
#pragma unroll
        for (int b = 0; b < 2; ++b)
#pragma unroll
            for (int c = 0; c < 4; ++c) {
                dz[a][b][c] = 0.f; dr[a][b][c] = 0.f;
                dxh[a][b][c] = 0.f; drh[a][b][c] = 0.f;
            }

    const __half* ArowX = Xt + (size_t)mt * 128 * 512;
    const __half* ArowH = hpack_in + (size_t)mt * 128 * 512;

    load_stage(sb, ArowX, Wp, jt, 0, tid);
    cp_commit();

    const uint32_t aoff = (uint32_t)((wm * 32 + (lane & 15)) * ROWB + (lane >> 4) * 16);
    const uint32_t boff = (uint32_t)((wn * 48 + (lane & 7) + ((lane >> 4) << 3)) * ROWB + ((lane >> 3) & 1) * 16);

    // ---------------- phase 0: x_t @ W ----------------
#pragma unroll 2
    for (int s = 0; s < 8; ++s) {
        if (s < 7) {
            load_stage(sb + ((s + 1) & 1) * STAGE_BYTES, ArowX, Wp, jt, (s + 1) * 64, tid);
            cp_commit();
            cp_wait<1>();
        } else if (!first) {
            // prefetch phase-1 stage 0 (global stage 8, buffer 0)
            load_stage(sb + ((s + 1) & 1) * STAGE_BYTES, ArowH, Up, jt, 0, tid);
            cp_commit();
            cp_wait<1>();
        } else {
            cp_wait<0>();
        }
        __syncthreads();
        uint32_t stg = sb + (s & 1) * STAGE_BYTES;
        STAGE_MMA(dxh);
        __syncthreads();
    }

    // ---------------- phase 1: h @ U ----------------
    if (!first) {
#pragma unroll 2
        for (int s = 0; s < 8; ++s) {
            if (s < 7) {
                load_stage(sb + ((s + 1) & 1) * STAGE_BYTES, ArowH, Up, jt, (s + 1) * 64, tid);
                cp_commit();
                cp_wait<1>();
            } else {
                cp_wait<0>();
            }
            __syncthreads();
            uint32_t stg = sb + (s & 1) * STAGE_BYTES;   // global stage 8+s, parity s&1
            STAGE_MMA(drh);
            __syncthreads();
        }
    }

    // ---------------- gate epilogue ----------------
#pragma unroll
    for (int mi = 0; mi < 2; ++mi)
#pragma unroll
        for (int rh = 0; rh < 2; ++rh) {
            int mg = mt * 128 + wm * 32 + mi * 16 + (lane >> 2) + rh * 8;
#pragma unroll
            for (int nj = 0; nj < 2; ++nj) {
                int cb   = nj * 8 + (lane & 3) * 2;
                int colh = jt * 32 + wn * 16 + cb;
                float2 hp = make_float2(0.f, 0.f);
                if (!first) hp = *(const float2*)(hprev + (size_t)mg * 512 + colh);
                float2 b0z = *(const float2*)(bias + colh);
                float2 b1z = *(const float2*)(bias + 1536 + colh);
                float2 b0r = *(const float2*)(bias + 512 + colh);
                float2 b1r = *(const float2*)(bias + 2048 + colh);
                float2 b0h = *(const float2*)(bias + 1024 + colh);
                float2 b1h = *(const float2*)(bias + 2560 + colh);
                float hpv[2] = {hp.x, hp.y};
                float b0zv[2] = {b0z.x, b0z.y}, b1zv[2] = {b1z.x, b1z.y};
                float b0rv[2] = {b0r.x, b0r.y}, b1rv[2] = {b1r.x, b1r.y};
                float b0hv[2] = {b0h.x, b0h.y}, b1hv[2] = {b1h.x, b1h.y};
                float hn[2];
#pragma unroll
                for (int cc = 0; cc < 2; ++cc) {
                    int r = rh * 2 + cc;
                    float zp  = dz[mi][nj][r] + b0zv[cc] + b1zv[cc];
                    float rp  = dr[mi][nj][r] + b0rv[cc] + b1rv[cc];
                    float xhp = dxh[mi][nj][r] + b0hv[cc];
                    float rhp = drh[mi][nj][r] + b1hv[cc];
                    float z  = sigmoidf_(zp);
                    float rg = sigmoidf_(rp);
                    float hh = fmaxf(xhp + rg * rhp, 0.f);
                    hn[cc] = z * hpv[cc] + (1.f - z) * hh;
                }
                *(float2*)(hout + (size_t)mg * 512 + colh) = make_float2(hn[0], hn[1]);
                if (!last)
                    *(__half2*)(hpk + (size_t)mg * 512 + colh) =
                        __halves2half2(__float2half_rn(hn[0]), __float2half_rn(hn[1]));
            }
        }
}

// ---------------- host ----------------
extern "C" void kernel_launch(void* const* d_in, const int* in_sizes, int n_in,
                              void* d_out, int out_size) {
    const float* x = (const float*)d_in[0];
    const float* W = (const float*)d_in[1];
    const float* U = (const float*)d_in[2];
    const float* b = (const float*)d_in[3];
    float* out = (float*)d_out;

    __half *Xp, *Wp, *Up, *Hp0;
    float *Hf0;
    cudaGetSymbolAddress((void**)&Xp, g_xp16);
    cudaGetSymbolAddress((void**)&Wp, g_wp16);
    cudaGetSymbolAddress((void**)&Up, g_up16);
    cudaGetSymbolAddress((void**)&Hf0, g_hf);
    cudaGetSymbolAddress((void**)&Hp0, g_hp16);
    float*  Hf[2] = {Hf0, Hf0 + (size_t)NSEQ * 512};
    __half* Hp[2] = {Hp0, Hp0 + (size_t)NSEQ * 512};

    static int smem_set = 0;
    if (!smem_set) {
        cudaFuncSetAttribute(gru_fused, cudaFuncAttributeMaxDynamicSharedMemorySize, SMEM_BYTES);
        smem_set = 1;
    }

    pack_wu16<<<dim3(384, 2), 256>>>(W, U, Wp, Up);
    pack_x16<<<16384, 256>>>(x, Xp);

    for (int t = 0; t < PT_; ++t) {
        const __half* Xt   = Xp + (size_t)t * 4096u * 512u;
        const __half* Ahp  = Hp[(t + 1) & 1];
        const float* hprev = Hf[(t + 1) & 1];
        float* ho = (t == PT_ - 1) ? out : Hf[t & 1];
        gru_fused<<<dim3(16, 32), 256, SMEM_BYTES>>>(
            Xt, Wp, Up, b, Ahp, hprev, ho, Hp[t & 1],
            t == 0 ? 1 : 0, t == PT_ - 1 ? 1 : 0);
    }
    (void)in_sizes; (void)n_in; (void)out_size;
}